// round 2
// baseline (speedup 1.0000x reference)
#include <cuda_runtime.h>
#include <math.h>

#define HEADS 4
#define BB 8
#define NN 1024
#define CC 256
#define DD 64
#define TM 32      // query rows per CTA
#define TK 64      // keys per chunk
#define SP 1028    // sS row pitch (floats), 16B-aligned rows, bank-staggered
#define KP 68      // sK/sV row pitch (floats), 16B-aligned rows

#define NEGINF __int_as_float(0xff800000)

__global__ __launch_bounds__(256, 1)
void attn_fused_kernel(const float* __restrict__ q,
                       const float* __restrict__ k,
                       const float* __restrict__ v,
                       const unsigned int* __restrict__ mask,   // bool widened to 32-bit
                       const float* __restrict__ dis,
                       float* __restrict__ out,    // [B,N,C]
                       float* __restrict__ pout)   // [H,B,N,N]
{
    extern __shared__ float sm[];
    float* sS = sm;                    // TM * SP
    float* sQ = sm + TM * SP;          // TM * DD
    float* sK = sQ + TM * DD;          // TK * KP (reused as sV)

    const int tid = threadIdx.x;
    const int rowTile = blockIdx.x;    // 0..31
    const int b = blockIdx.y;          // 0..7
    const int h = blockIdx.z;          // 0..3
    const int row0 = rowTile * TM;

    const float* qbase = q + ((size_t)b * NN) * CC + h * DD;
    const float* kbase = k + ((size_t)b * NN) * CC + h * DD;
    const float* vbase = v + ((size_t)b * NN) * CC + h * DD;
    const float* disbase = dis + ((size_t)b * NN + row0) * NN;
    const unsigned int* mbase = mask + ((size_t)b * NN + row0) * NN;

    // ---- Load Q tile [TM x DD] into smem ----
    {
        int r  = tid >> 3;             // 0..31
        int kk = (tid & 7) * 8;        // 0..56
        const float4* g = (const float4*)(qbase + (size_t)(row0 + r) * CC + kk);
        float4 a0 = g[0];
        float4 a1 = g[1];
        *(float4*)(sQ + r * DD + kk)     = a0;
        *(float4*)(sQ + r * DD + kk + 4) = a1;
    }
    __syncthreads();

    // Thread tiling for score phase: 16x16 thread grid
    const int ry = tid >> 4;           // 0..15
    const int cx = tid & 15;           // 0..15
    const int r0 = 2 * ry;
    const int r1 = 2 * ry + 1;

    // ==== Phase 1: S = (Q K^T + dis)/8, masked -> sS ====
    for (int kc = 0; kc < NN / TK; kc++) {
        // load K chunk [TK keys][DD] (natural layout)
        {
            int key = tid >> 2;                // 0..63
            int kk  = (tid & 3) * 16;          // 0,16,32,48
            const float4* g = (const float4*)(kbase + (size_t)(kc * TK + key) * CC + kk);
            float4* s = (float4*)(sK + key * KP + kk);
            #pragma unroll
            for (int i = 0; i < 4; i++) s[i] = g[i];
        }
        __syncthreads();

        float acc0[4] = {0.f, 0.f, 0.f, 0.f};
        float acc1[4] = {0.f, 0.f, 0.f, 0.f};
        #pragma unroll
        for (int kq = 0; kq < DD / 4; kq++) {
            float4 q0 = *(const float4*)(sQ + r0 * DD + 4 * kq);
            float4 q1 = *(const float4*)(sQ + r1 * DD + 4 * kq);
            #pragma unroll
            for (int j = 0; j < 4; j++) {
                int c = cx + 16 * j;           // conflict-free column stride
                float4 kv = *(const float4*)(sK + c * KP + 4 * kq);
                acc0[j] = fmaf(q0.x, kv.x, acc0[j]);
                acc0[j] = fmaf(q0.y, kv.y, acc0[j]);
                acc0[j] = fmaf(q0.z, kv.z, acc0[j]);
                acc0[j] = fmaf(q0.w, kv.w, acc0[j]);
                acc1[j] = fmaf(q1.x, kv.x, acc1[j]);
                acc1[j] = fmaf(q1.y, kv.y, acc1[j]);
                acc1[j] = fmaf(q1.z, kv.z, acc1[j]);
                acc1[j] = fmaf(q1.w, kv.w, acc1[j]);
            }
        }

        // apply dis, scale, mask; store into sS at global column
        #pragma unroll
        for (int j = 0; j < 4; j++) {
            int c = kc * TK + cx + 16 * j;     // 0..1023
            float d0 = __ldg(disbase + (size_t)r0 * NN + c);
            float d1 = __ldg(disbase + (size_t)r1 * NN + c);
            unsigned int m0 = __ldg(mbase + (size_t)r0 * NN + c);
            unsigned int m1 = __ldg(mbase + (size_t)r1 * NN + c);
            float s0 = (acc0[j] + d0) * 0.125f;
            float s1 = (acc1[j] + d1) * 0.125f;
            if (m0 != 0u) s0 = NEGINF;
            if (m1 != 0u) s1 = NEGINF;
            sS[r0 * SP + c] = s0;
            sS[r1 * SP + c] = s1;
        }
        __syncthreads();   // protect sK for next chunk
    }

    // ==== Phase 2: softmax rows of sS (in-place) ====
    {
        int r   = tid >> 3;                    // 0..31
        int seg = tid & 7;                     // 0..7
        float* rowp = sS + r * SP;
        float mx = NEGINF;
        for (int i = seg; i < NN; i += 8) mx = fmaxf(mx, rowp[i]);
        #pragma unroll
        for (int o = 1; o < 8; o <<= 1) mx = fmaxf(mx, __shfl_xor_sync(0xffffffffu, mx, o));
        float sum = 0.f;
        for (int i = seg; i < NN; i += 8) {
            float e = expf(rowp[i] - mx);
            rowp[i] = e;
            sum += e;
        }
        #pragma unroll
        for (int o = 1; o < 8; o <<= 1) sum += __shfl_xor_sync(0xffffffffu, sum, o);
        float inv = 1.0f / sum;
        for (int i = seg; i < NN; i += 8) rowp[i] *= inv;
    }
    __syncthreads();

    // ==== Phase 3: write p_attn tile (coalesced float4) ====
    {
        float* pbase = pout + (((size_t)h * BB + b) * NN + row0) * NN;
        for (int i = tid; i < TM * (NN / 4); i += 256) {
            int r  = i >> 8;                   // /256
            int m4 = i & 255;
            float4 val = *(const float4*)(sS + r * SP + 4 * m4);
            *(float4*)(pbase + (size_t)r * NN + 4 * m4) = val;
        }
    }

    // ==== Phase 4: O = P @ V ====
    const int cc = 4 * cx;                     // consecutive 4 output cols
    float o0[4] = {0.f, 0.f, 0.f, 0.f};
    float o1[4] = {0.f, 0.f, 0.f, 0.f};

    for (int kc = 0; kc < NN / TK; kc++) {
        __syncthreads();                       // protect sK reuse
        {
            int key = tid >> 2;
            int kk  = (tid & 3) * 16;
            const float4* g = (const float4*)(vbase + (size_t)(kc * TK + key) * CC + kk);
            float4* s = (float4*)(sK + key * KP + kk);
            #pragma unroll
            for (int i = 0; i < 4; i++) s[i] = g[i];
        }
        __syncthreads();

        #pragma unroll 4
        for (int m = 0; m < TK; m += 4) {
            int gm = kc * TK + m;
            float4 p0 = *(const float4*)(sS + r0 * SP + gm);
            float4 p1 = *(const float4*)(sS + r1 * SP + gm);
            #pragma unroll
            for (int i = 0; i < 4; i++) {
                float4 vv = *(const float4*)(sK + (m + i) * KP + cc);
                float pp0 = (i == 0) ? p0.x : (i == 1) ? p0.y : (i == 2) ? p0.z : p0.w;
                float pp1 = (i == 0) ? p1.x : (i == 1) ? p1.y : (i == 2) ? p1.z : p1.w;
                o0[0] = fmaf(pp0, vv.x, o0[0]);
                o0[1] = fmaf(pp0, vv.y, o0[1]);
                o0[2] = fmaf(pp0, vv.z, o0[2]);
                o0[3] = fmaf(pp0, vv.w, o0[3]);
                o1[0] = fmaf(pp1, vv.x, o1[0]);
                o1[1] = fmaf(pp1, vv.y, o1[1]);
                o1[2] = fmaf(pp1, vv.z, o1[2]);
                o1[3] = fmaf(pp1, vv.w, o1[3]);
            }
        }
    }

    // write O tile: rows r0,r1; cols cc..cc+3 of this head's slice
    {
        float* obase = out + ((size_t)b * NN) * CC + h * DD;
        float4 w0 = make_float4(o0[0], o0[1], o0[2], o0[3]);
        float4 w1 = make_float4(o1[0], o1[1], o1[2], o1[3]);
        *(float4*)(obase + (size_t)(row0 + r0) * CC + cc) = w0;
        *(float4*)(obase + (size_t)(row0 + r1) * CC + cc) = w1;
    }
}

extern "C" void kernel_launch(void* const* d_in, const int* in_sizes, int n_in,
                              void* d_out, int out_size) {
    const float* q = (const float*)d_in[0];
    const float* k = (const float*)d_in[1];
    const float* v = (const float*)d_in[2];
    const unsigned int* mask = (const unsigned int*)d_in[3];
    const float* dis = (const float*)d_in[4];

    float* out  = (float*)d_out;                       // [B,N,C] first
    float* pout = out + (size_t)BB * NN * CC;          // then [H,B,N,N]

    size_t smem = (size_t)(TM * SP + TM * DD + TK * KP) * sizeof(float);
    cudaFuncSetAttribute(attn_fused_kernel,
                         cudaFuncAttributeMaxDynamicSharedMemorySize, (int)smem);

    dim3 grid(NN / TM, BB, HEADS);
    attn_fused_kernel<<<grid, 256, smem>>>(q, k, v, mask, dis, out, pout);
}

// round 6
// speedup vs baseline: 2.1312x; 2.1312x over previous
#include <cuda_runtime.h>
#include <math.h>
#include <stdint.h>

#define HEADS 4
#define BB 8
#define NN 1024
#define CC 256
#define DD 64
#define QT 128          // queries per CTA
#define NC 128          // keys per chunk
#define NCHUNK 8

#define QP 68           // sQ pitch (floats): 68 % 32 == 4 -> conflict-free frags
#define KP 68
#define VP 72           // 72 % 32 == 8 -> conflict-free B frags
#define DMP 132         // dis/mask/P staging pitch: 132 % 32 == 4

// float-index offsets in dynamic smem
#define SQ_F   0
#define SK_F   (SQ_F + QT*QP)          // 8704
#define SV_F   (SK_F + NC*KP)          // 17408
#define SDM_F  (SV_F + NC*VP)          // 26624
#define RS_F   (SDM_F + QT*DMP)        // 43520
#define SMEM_FLOATS (RS_F + 128)
#define SMEM_BYTES  (SMEM_FLOATS * 4)  // 174592 bytes

#define NEGINF __int_as_float(0xff800000)

static __device__ __forceinline__ uint32_t f2tf32(float f){
    uint32_t u; asm("cvt.rna.tf32.f32 %0, %1;" : "=r"(u) : "f"(f)); return u;
}

static __device__ __forceinline__ void mma_tf32(float* c, const uint32_t* a,
                                                uint32_t b0, uint32_t b1){
    asm volatile("mma.sync.aligned.m16n8k8.row.col.f32.tf32.tf32.f32 "
        "{%0,%1,%2,%3}, {%4,%5,%6,%7}, {%8,%9}, {%0,%1,%2,%3};"
        : "+f"(c[0]), "+f"(c[1]), "+f"(c[2]), "+f"(c[3])
        : "r"(a[0]), "r"(a[1]), "r"(a[2]), "r"(a[3]), "r"(b0), "r"(b1));
}

// S[32x64 warp tile] = Q Kt for one 128-key chunk
static __device__ __forceinline__ void compute_S(const uint32_t* __restrict__ sQu,
                                                 const uint32_t* __restrict__ sKu,
                                                 int rw0, int cw0, int lane,
                                                 float sacc[2][8][4]){
    #pragma unroll
    for (int rt = 0; rt < 2; rt++)
        #pragma unroll
        for (int ct = 0; ct < 8; ct++)
            #pragma unroll
            for (int i = 0; i < 4; i++) sacc[rt][ct][i] = 0.0f;

    #pragma unroll
    for (int kt = 0; kt < 8; kt++){
        const int k0 = 8*kt + (lane & 3);
        uint32_t a[2][4];
        #pragma unroll
        for (int rt = 0; rt < 2; rt++){
            const uint32_t* q0 = sQu + (rw0 + 16*rt + (lane >> 2)) * QP + k0;
            a[rt][0] = q0[0];
            a[rt][1] = q0[8*QP];
            a[rt][2] = q0[4];
            a[rt][3] = q0[8*QP + 4];
        }
        #pragma unroll
        for (int ct = 0; ct < 8; ct++){
            const uint32_t* kp = sKu + (cw0 + 8*ct + (lane >> 2)) * KP + k0;
            uint32_t b0 = kp[0], b1 = kp[4];
            mma_tf32(sacc[0][ct], a[0], b0, b1);
            mma_tf32(sacc[1][ct], a[1], b0, b1);
        }
    }
}

__global__ __launch_bounds__(256, 1)
void attn_hmma_kernel(const float* __restrict__ q,
                      const float* __restrict__ k,
                      const float* __restrict__ v,
                      const unsigned int* __restrict__ mask,
                      const float* __restrict__ dis,
                      float* __restrict__ out,
                      float* __restrict__ pout)
{
    extern __shared__ float smf[];
    uint32_t* smu = (uint32_t*)smf;

    const int tid  = threadIdx.x;
    const int wid  = tid >> 5;
    const int lane = tid & 31;
    const int h    = blockIdx.x & 3;        // heads fastest -> dis/mask L2 reuse
    const int tile = blockIdx.x >> 2;
    const int b    = blockIdx.y;
    const int row0 = tile * QT;

    const float* qbase = q + ((size_t)b * NN + row0) * CC + h * DD;
    const float* kbase = k + ((size_t)b * NN) * CC + h * DD;
    const float* vbase = v + ((size_t)b * NN) * CC + h * DD;
    const float* disbase = dis + ((size_t)b * NN + row0) * NN;
    const unsigned int* mbase = mask + ((size_t)b * NN + row0) * NN;
    float* pbase = pout + (((size_t)h * BB + b) * NN + row0) * NN;

    // warp tiles
    const int rw0 = (wid >> 1) * 32;        // S + PV rows
    const int cw0 = (wid & 1) * 64;         // S cols (keys)
    const int dv0 = (wid & 1) * 32;         // PV cols (d)

    // rowsum init
    if (tid < 128) smf[RS_F + tid] = 0.0f;

    // ---- stage Q once (fp32 -> tf32 rna) ----
    {
        int r = tid >> 1, hf = (tid & 1) * 32;
        const float4* s = (const float4*)(qbase + (size_t)r * CC + hf);
        uint32_t* d = smu + SQ_F + r * QP + hf;
        #pragma unroll
        for (int i = 0; i < 8; i++){
            float4 vv = s[i];
            uint4 o; o.x=f2tf32(vv.x); o.y=f2tf32(vv.y); o.z=f2tf32(vv.z); o.w=f2tf32(vv.w);
            *(uint4*)(d + 4*i) = o;
        }
    }

    const int stg_r = tid >> 1, stg_h = (tid & 1) * 32;   // K/V staging coords
    const int dm_r  = tid >> 5, dm_c = tid & 31;          // dis/mask staging coords

    float psum[2][2] = {{0.f,0.f},{0.f,0.f}};

    // ================= PASS 1: row sums =================
    for (int kc = 0; kc < NCHUNK; kc++){
        __syncthreads();
        // stage K chunk
        {
            const float4* s = (const float4*)(kbase + (size_t)(kc*NC + stg_r) * CC + stg_h);
            uint32_t* d = smu + SK_F + stg_r * KP + stg_h;
            #pragma unroll
            for (int i = 0; i < 8; i++){
                float4 vv = s[i];
                uint4 o; o.x=f2tf32(vv.x); o.y=f2tf32(vv.y); o.z=f2tf32(vv.z); o.w=f2tf32(vv.w);
                *(uint4*)(d + 4*i) = o;
            }
        }
        // stage merged dis/mask
        #pragma unroll 4
        for (int it = 0; it < 16; it++){
            int r = dm_r + 8*it;
            float4 dv = *(const float4*)(disbase + (size_t)r * NN + kc*NC + 4*dm_c);
            uint4  mv = *(const uint4*) (mbase   + (size_t)r * NN + kc*NC + 4*dm_c);
            if (mv.x) dv.x = NEGINF;
            if (mv.y) dv.y = NEGINF;
            if (mv.z) dv.z = NEGINF;
            if (mv.w) dv.w = NEGINF;
            *(float4*)(smf + SDM_F + r*DMP + 4*dm_c) = dv;
        }
        __syncthreads();

        float sacc[2][8][4];
        compute_S(smu + SQ_F, smu + SK_F, rw0, cw0, lane, sacc);

        #pragma unroll
        for (int rt = 0; rt < 2; rt++){
            int row = rw0 + 16*rt + (lane >> 2);
            #pragma unroll
            for (int ct = 0; ct < 8; ct++){
                int col = cw0 + 8*ct + 2*(lane & 3);
                float2 d0 = *(const float2*)(smf + SDM_F + row*DMP + col);
                float2 d1 = *(const float2*)(smf + SDM_F + (row+8)*DMP + col);
                psum[rt][0] += __expf((sacc[rt][ct][0] + d0.x) * 0.125f)
                             + __expf((sacc[rt][ct][1] + d0.y) * 0.125f);
                psum[rt][1] += __expf((sacc[rt][ct][2] + d1.x) * 0.125f)
                             + __expf((sacc[rt][ct][3] + d1.y) * 0.125f);
            }
        }
    }
    // reduce rowsums: quad shuffle then smem atomic (col halves from 2 warps)
    #pragma unroll
    for (int rt = 0; rt < 2; rt++)
        #pragma unroll
        for (int hf = 0; hf < 2; hf++){
            float vsum = psum[rt][hf];
            vsum += __shfl_xor_sync(0xffffffffu, vsum, 1);
            vsum += __shfl_xor_sync(0xffffffffu, vsum, 2);
            if ((lane & 3) == 0)
                atomicAdd(smf + RS_F + rw0 + 16*rt + 8*hf + (lane >> 2), vsum);
        }
    __syncthreads();
    float inv[2][2];
    #pragma unroll
    for (int rt = 0; rt < 2; rt++)
        #pragma unroll
        for (int hf = 0; hf < 2; hf++)
            inv[rt][hf] = 1.0f / smf[RS_F + rw0 + 16*rt + 8*hf + (lane >> 2)];

    // ================= PASS 2: P + O =================
    float oacc[2][4][4];
    #pragma unroll
    for (int rt = 0; rt < 2; rt++)
        #pragma unroll
        for (int dt = 0; dt < 4; dt++)
            #pragma unroll
            for (int i = 0; i < 4; i++) oacc[rt][dt][i] = 0.0f;

    for (int kc = 0; kc < NCHUNK; kc++){
        __syncthreads();
        // stage K chunk
        {
            const float4* s = (const float4*)(kbase + (size_t)(kc*NC + stg_r) * CC + stg_h);
            uint32_t* d = smu + SK_F + stg_r * KP + stg_h;
            #pragma unroll
            for (int i = 0; i < 8; i++){
                float4 vv = s[i];
                uint4 o; o.x=f2tf32(vv.x); o.y=f2tf32(vv.y); o.z=f2tf32(vv.z); o.w=f2tf32(vv.w);
                *(uint4*)(d + 4*i) = o;
            }
        }
        // stage V chunk (natural layout, pitch 72)
        {
            const float4* s = (const float4*)(vbase + (size_t)(kc*NC + stg_r) * CC + stg_h);
            uint32_t* d = smu + SV_F + stg_r * VP + stg_h;
            #pragma unroll
            for (int i = 0; i < 8; i++){
                float4 vv = s[i];
                uint4 o; o.x=f2tf32(vv.x); o.y=f2tf32(vv.y); o.z=f2tf32(vv.z); o.w=f2tf32(vv.w);
                *(uint4*)(d + 4*i) = o;
            }
        }
        // stage merged dis/mask
        #pragma unroll 4
        for (int it = 0; it < 16; it++){
            int r = dm_r + 8*it;
            float4 dv = *(const float4*)(disbase + (size_t)r * NN + kc*NC + 4*dm_c);
            uint4  mv = *(const uint4*) (mbase   + (size_t)r * NN + kc*NC + 4*dm_c);
            if (mv.x) dv.x = NEGINF;
            if (mv.y) dv.y = NEGINF;
            if (mv.z) dv.z = NEGINF;
            if (mv.w) dv.w = NEGINF;
            *(float4*)(smf + SDM_F + r*DMP + 4*dm_c) = dv;
        }
        __syncthreads();

        float sacc[2][8][4];
        compute_S(smu + SQ_F, smu + SK_F, rw0, cw0, lane, sacc);

        // exp -> normalized P (tf32-rna bits) back into SDM staging
        #pragma unroll
        for (int rt = 0; rt < 2; rt++){
            int row = rw0 + 16*rt + (lane >> 2);
            #pragma unroll
            for (int ct = 0; ct < 8; ct++){
                int col = cw0 + 8*ct + 2*(lane & 3);
                float2 d0 = *(const float2*)(smf + SDM_F + row*DMP + col);
                float2 d1 = *(const float2*)(smf + SDM_F + (row+8)*DMP + col);
                uint32_t p0 = f2tf32(__expf((sacc[rt][ct][0] + d0.x) * 0.125f) * inv[rt][0]);
                uint32_t p1 = f2tf32(__expf((sacc[rt][ct][1] + d0.y) * 0.125f) * inv[rt][0]);
                uint32_t p2 = f2tf32(__expf((sacc[rt][ct][2] + d1.x) * 0.125f) * inv[rt][1]);
                uint32_t p3 = f2tf32(__expf((sacc[rt][ct][3] + d1.y) * 0.125f) * inv[rt][1]);
                *(uint2*)(smu + SDM_F + row*DMP + col)     = make_uint2(p0, p1);
                *(uint2*)(smu + SDM_F + (row+8)*DMP + col) = make_uint2(p2, p3);
            }
        }
        __syncthreads();

        // PV: O[32 x 32] += P[32 x 128] * V[128 x 32]
        #pragma unroll
        for (int kt = 0; kt < 16; kt++){
            const int k0 = 8*kt + (lane & 3);
            uint32_t a[2][4];
            #pragma unroll
            for (int rt = 0; rt < 2; rt++){
                const uint32_t* pp = smu + SDM_F + (rw0 + 16*rt + (lane >> 2)) * DMP + k0;
                a[rt][0] = pp[0];
                a[rt][1] = pp[8*DMP];
                a[rt][2] = pp[4];
                a[rt][3] = pp[8*DMP + 4];
            }
            #pragma unroll
            for (int dt = 0; dt < 4; dt++){
                int dcol = dv0 + 8*dt + (lane >> 2);
                uint32_t b0 = smu[SV_F + (size_t)k0 * VP + dcol];
                uint32_t b1 = smu[SV_F + (size_t)(k0 + 4) * VP + dcol];
                mma_tf32(oacc[0][dt], a[0], b0, b1);
                mma_tf32(oacc[1][dt], a[1], b0, b1);
            }
        }

        // coalesced p_attn store (reads SDM, concurrent with nothing hazardous)
        #pragma unroll 4
        for (int it = 0; it < 16; it++){
            int r = dm_r + 8*it;
            float4 pv4 = *(const float4*)(smf + SDM_F + r*DMP + 4*dm_c);
            *(float4*)(pbase + (size_t)r * NN + kc*NC + 4*dm_c) = pv4;
        }
    }

    // ---- write O ----
    #pragma unroll
    for (int rt = 0; rt < 2; rt++){
        int gr = row0 + rw0 + 16*rt + (lane >> 2);
        #pragma unroll
        for (int dt = 0; dt < 4; dt++){
            int gc = h * DD + dv0 + 8*dt + 2*(lane & 3);
            float* o0 = out + ((size_t)b * NN + gr) * CC + gc;
            *(float2*)o0            = make_float2(oacc[rt][dt][0], oacc[rt][dt][1]);
            *(float2*)(o0 + 8*CC)   = make_float2(oacc[rt][dt][2], oacc[rt][dt][3]);
        }
    }
}

extern "C" void kernel_launch(void* const* d_in, const int* in_sizes, int n_in,
                              void* d_out, int out_size) {
    const float* q = (const float*)d_in[0];
    const float* k = (const float*)d_in[1];
    const float* v = (const float*)d_in[2];
    const unsigned int* mask = (const unsigned int*)d_in[3];
    const float* dis = (const float*)d_in[4];

    float* out  = (float*)d_out;
    float* pout = out + (size_t)BB * NN * CC;

    cudaFuncSetAttribute(attn_hmma_kernel,
                         cudaFuncAttributeMaxDynamicSharedMemorySize, SMEM_BYTES);

    dim3 grid(HEADS * (NN / QT), BB, 1);
    attn_hmma_kernel<<<grid, 256, SMEM_BYTES>>>(q, k, v, mask, dis, out, pout);
}